// round 7
// baseline (speedup 1.0000x reference)
#include <cuda_runtime.h>
#include <cuda_fp16.h>
#include <cstdint>

// Problem dims
#define BATCH   8192
#define CH_H    2048
#define DIM     6144
#define CHUNK   512
#define NCHUNK  12
#define EPSBN   1e-5f
#define SPLITS  64

// GEMM tiling (128x128 tile, 2-stage, 2 CTAs/SM)
#define BM 128
#define BN 128
#define STAGES 2
#define MAT_BYTES 16384              // 128 rows x 128 B (64 fp16)
#define STAGE_BYTES (3 * MAT_BYTES)  // Ah, Al, Bh = 49152
#define SMEM_GEMM (STAGES * STAGE_BYTES)   // 98304 -> 2 CTAs/SM

// ---------------- scratch ----------------
__device__ float g_buf0[(size_t)BATCH * CH_H];
__device__ float g_psum[SPLITS * CH_H];
__device__ float g_psq [SPLITS * CH_H];
__device__ float g_scale[CH_H];
__device__ float g_shift[CH_H];
__device__ __half g_Ah[(size_t)BATCH * DIM];
__device__ __half g_Al[(size_t)BATCH * DIM];
__device__ __half g_Bh[(size_t)DIM * CH_H];

// ---------------- helpers ----------------
__device__ __forceinline__ uint32_t smem_u32(const void* p) {
    uint32_t a;
    asm("{ .reg .u64 t; cvta.to.shared.u64 t, %1; cvt.u32.u64 %0, t; }" : "=r"(a) : "l"(p));
    return a;
}
__device__ __forceinline__ void cp16(uint32_t s, const void* g) {
    asm volatile("cp.async.cg.shared.global [%0], [%1], 16;" :: "r"(s), "l"(g));
}
#define CP_COMMIT() asm volatile("cp.async.commit_group;" ::: "memory")
#define CP_WAIT1()  asm volatile("cp.async.wait_group 1;" ::: "memory")

__device__ __forceinline__ void ldmx4(uint32_t* r, uint32_t addr) {
    asm volatile("ldmatrix.sync.aligned.m8n8.x4.shared.b16 {%0,%1,%2,%3}, [%4];"
                 : "=r"(r[0]), "=r"(r[1]), "=r"(r[2]), "=r"(r[3]) : "r"(addr));
}
__device__ __forceinline__ void mma16816(float* d, const uint32_t* a, const uint32_t* b) {
    asm volatile("mma.sync.aligned.m16n8k16.row.col.f32.f16.f16.f32 "
                 "{%0,%1,%2,%3}, {%4,%5,%6,%7}, {%8,%9}, {%0,%1,%2,%3};"
                 : "+f"(d[0]), "+f"(d[1]), "+f"(d[2]), "+f"(d[3])
                 : "r"(a[0]), "r"(a[1]), "r"(a[2]), "r"(a[3]), "r"(b[0]), "r"(b[1]));
}
__device__ __forceinline__ void split2h(float f0, float f1, uint32_t& hp, uint32_t& lp) {
    __half h0 = __float2half_rn(f0);
    __half h1 = __float2half_rn(f1);
    __half l0 = __float2half_rn(f0 - __half2float(h0));
    __half l1 = __float2half_rn(f1 - __half2float(h1));
    hp = (uint32_t)__half_as_ushort(h0) | ((uint32_t)__half_as_ushort(h1) << 16);
    lp = (uint32_t)__half_as_ushort(l0) | ((uint32_t)__half_as_ushort(l1) << 16);
}
__device__ __forceinline__ uint32_t pack2h(float f0, float f1) {
    __half h0 = __float2half_rn(f0);
    __half h1 = __float2half_rn(f1);
    return (uint32_t)__half_as_ushort(h0) | ((uint32_t)__half_as_ushort(h1) << 16);
}

// ---------------- zero init ----------------
__global__ __launch_bounds__(256) void zero_kernel(float4* __restrict__ p) {
    p[(size_t)blockIdx.x * 256 + threadIdx.x] = make_float4(0.f, 0.f, 0.f, 0.f);
}

// ---------------- score + reweight + pack A (layer-1 input) ----------------
__global__ __launch_bounds__(512) void score_pack(
    const float* __restrict__ ft0, const float* __restrict__ ft1,
    const float* __restrict__ ft2, const float* __restrict__ key,
    float* __restrict__ ft_all, __half* __restrict__ Ah, __half* __restrict__ Al)
{
    const int row = blockIdx.x, t = threadIdx.x;
    const int warp = t >> 5, lane = t & 31;
    __shared__ float wsum[16];
    __shared__ float sc[NCHUNK];
    const float kv = key[t];
    float x[NCHUNK];
#pragma unroll
    for (int c = 0; c < NCHUNK; ++c) {
        const float* src = (c < 4) ? ft0 : ((c < 8) ? ft1 : ft2);
        x[c] = src[(size_t)row * CH_H + (c & 3) * CHUNK + t];
    }
#pragma unroll
    for (int c = 0; c < NCHUNK; ++c) {
        float p = x[c] * kv;
#pragma unroll
        for (int o = 16; o; o >>= 1) p += __shfl_xor_sync(0xffffffffu, p, o);
        if (lane == 0) wsum[warp] = p;
        __syncthreads();
        if (warp == 0) {
            float q = (lane < 16) ? wsum[lane] : 0.f;
#pragma unroll
            for (int o = 8; o; o >>= 1) q += __shfl_xor_sync(0xffffffffu, q, o);
            if (lane == 0) sc[c] = q;
        }
        __syncthreads();
    }
    float mx = sc[0];
#pragma unroll
    for (int c = 1; c < NCHUNK; ++c) mx = fmaxf(mx, sc[c]);
    float e[NCHUNK], s = 0.f;
#pragma unroll
    for (int c = 0; c < NCHUNK; ++c) { e[c] = expf(sc[c] - mx); s += e[c]; }
    const float inv = 1.0f / s;
#pragma unroll
    for (int c = 0; c < NCHUNK; ++c) {
        float v = x[c] * (1.0f + e[c] * inv);
        size_t idx = (size_t)row * DIM + c * CHUNK + t;
        ft_all[idx] = v;
        __half h = __float2half_rn(v);
        Ah[idx] = h;
        Al[idx] = __float2half_rn(v - __half2float(h));
    }
}

// ---------------- layer-3 epilogue: in-place bias+relu, then pack ----------------
__global__ __launch_bounds__(256) void bias_relu_pack(
    float* __restrict__ Y, const float* __restrict__ bias,
    __half* __restrict__ Ah, __half* __restrict__ Al)
{
    size_t i = ((size_t)blockIdx.x * 256 + threadIdx.x) * 8;
    int col = (int)(i % CH_H);
    float4 y0 = *(const float4*)(Y + i);
    float4 y1 = *(const float4*)(Y + i + 4);
    float4 b0 = *(const float4*)(bias + col);
    float4 b1 = *(const float4*)(bias + col + 4);
    float f[8] = {
        fmaxf(y0.x + b0.x, 0.f), fmaxf(y0.y + b0.y, 0.f),
        fmaxf(y0.z + b0.z, 0.f), fmaxf(y0.w + b0.w, 0.f),
        fmaxf(y1.x + b1.x, 0.f), fmaxf(y1.y + b1.y, 0.f),
        fmaxf(y1.z + b1.z, 0.f), fmaxf(y1.w + b1.w, 0.f)};
    *(float4*)(Y + i)     = make_float4(f[0], f[1], f[2], f[3]);
    *(float4*)(Y + i + 4) = make_float4(f[4], f[5], f[6], f[7]);
    uint4 hp, lp;
    split2h(f[0], f[1], hp.x, lp.x);
    split2h(f[2], f[3], hp.y, lp.y);
    split2h(f[4], f[5], hp.z, lp.z);
    split2h(f[6], f[7], hp.w, lp.w);
    *(uint4*)((char*)Ah + i * 2) = hp;
    *(uint4*)((char*)Al + i * 2) = lp;
}

// ---------------- BN apply fused with A-pack ----------------
__global__ __launch_bounds__(256) void bn_pack(
    const float* __restrict__ Y, __half* __restrict__ Ah,
    __half* __restrict__ Al, int K)
{
    size_t i = ((size_t)blockIdx.x * 256 + threadIdx.x) * 8;
    int col = (int)(i % K);
    float4 y0 = *(const float4*)(Y + i);
    float4 y1 = *(const float4*)(Y + i + 4);
    float4 s0 = *(const float4*)(g_scale + col);
    float4 s1 = *(const float4*)(g_scale + col + 4);
    float4 h0 = *(const float4*)(g_shift + col);
    float4 h1 = *(const float4*)(g_shift + col + 4);
    float f[8] = {
        fmaf(y0.x, s0.x, h0.x), fmaf(y0.y, s0.y, h0.y),
        fmaf(y0.z, s0.z, h0.z), fmaf(y0.w, s0.w, h0.w),
        fmaf(y1.x, s1.x, h1.x), fmaf(y1.y, s1.y, h1.y),
        fmaf(y1.z, s1.z, h1.z), fmaf(y1.w, s1.w, h1.w)};
    uint4 hp, lp;
    split2h(f[0], f[1], hp.x, lp.x);
    split2h(f[2], f[3], hp.y, lp.y);
    split2h(f[4], f[5], hp.z, lp.z);
    split2h(f[6], f[7], hp.w, lp.w);
    *(uint4*)((char*)Ah + i * 2) = hp;
    *(uint4*)((char*)Al + i * 2) = lp;
}

// ---------------- pack W: fp32 [K,N] -> fp16 [N,K] (transpose) ----------
__global__ __launch_bounds__(256) void pack_W_t(
    const float* __restrict__ W, __half* __restrict__ Bh, int K, int N)
{
    __shared__ float sm[32][33];
    const int k0 = blockIdx.x * 32, n0 = blockIdx.y * 32;
    const int tx = threadIdx.x & 31, ty = threadIdx.x >> 5;
#pragma unroll
    for (int i = 0; i < 4; ++i)
        sm[ty + 8 * i][tx] = W[(size_t)(k0 + ty + 8 * i) * N + n0 + tx];
    __syncthreads();
    const int kp = threadIdx.x & 15;
    const int nb = threadIdx.x >> 4;
#pragma unroll
    for (int j = 0; j < 2; ++j) {
        int n = nb + j * 16;
        *(uint32_t*)&Bh[(size_t)(n0 + n) * K + k0 + kp * 2] =
            pack2h(sm[kp * 2][n], sm[kp * 2 + 1][n]);
    }
}

// ---------------- mma.sync GEMM, fp16 2-pass ------------------------------------
// MODE 0: plain store + bias. MODE 1: plain + bias + relu.
// MODE 2: split-K (gridDim.z halves), accumulate into zeroed C via red.add, no bias.
// Ks = K stride of A/B rows; Kl = K elements handled by one CTA.
template <int MODE>
__global__ __launch_bounds__(256, 2) void gemm_mma(
    const __half* __restrict__ Ah, const __half* __restrict__ Al,
    const __half* __restrict__ Bh,
    const float* __restrict__ bias, float* __restrict__ C,
    int N, int Ks, int Kl)
{
    extern __shared__ __align__(128) char smem[];
    const uint32_t sb = smem_u32(smem);
    const int tid = threadIdx.x, lane = tid & 31, wid = tid >> 5;
    const int wm = wid & 1, wn = wid >> 1;
    const int m0 = blockIdx.y * BM, n0 = blockIdx.x * BN;
    const int kOff = blockIdx.z * Kl;
    const int KT = Kl >> 6;

    const __half* g0 = Ah + (size_t)m0 * Ks + kOff;
    const __half* g1 = Al + (size_t)m0 * Ks + kOff;
    const __half* g2 = Bh + (size_t)n0 * Ks + kOff;

    float acc[4][4][4];
#pragma unroll
    for (int a = 0; a < 4; ++a)
#pragma unroll
        for (int b = 0; b < 4; ++b)
#pragma unroll
            for (int c = 0; c < 4; ++c) acc[a][b][c] = 0.f;

    auto load_stage = [&](int slot, int kt) {
        const uint32_t st = sb + slot * STAGE_BYTES;
        const int k0 = kt << 6;
        const __half* gs[3] = {g0, g1, g2};
#pragma unroll
        for (int mtx = 0; mtx < 3; ++mtx) {
            const uint32_t base = st + mtx * MAT_BYTES;
            const __half* g = gs[mtx];
#pragma unroll
            for (int i = 0; i < 4; ++i) {
                int q = tid + i * 256;
                int row = q >> 3, c = q & 7;
                uint32_t sa = base + (((row << 3) + (c ^ (row & 7))) << 4);
                cp16(sa, g + (size_t)row * Ks + k0 + c * 8);
            }
        }
    };

    load_stage(0, 0); CP_COMMIT();
    load_stage(1, 1); CP_COMMIT();

    for (int kt = 0; kt < KT; ++kt) {
        CP_WAIT1();
        __syncthreads();

        const uint32_t st = sb + (kt & 1) * STAGE_BYTES;
#pragma unroll
        for (int kk = 0; kk < 4; ++kk) {
            const int cA = (kk << 1) + (lane >> 4);
            uint32_t bfr[4][2];
#pragma unroll
            for (int half = 0; half < 2; ++half) {
                int row = wn * 32 + half * 16 + (lane & 15);
                uint32_t ad = st + 2 * MAT_BYTES + (((row << 3) + (cA ^ (row & 7))) << 4);
                uint32_t r[4];
                ldmx4(r, ad);
                bfr[half * 2][0] = r[0]; bfr[half * 2][1] = r[2];
                bfr[half * 2 + 1][0] = r[1]; bfr[half * 2 + 1][1] = r[3];
            }
            uint32_t afr[4][4];
            // hi pass
#pragma unroll
            for (int mi = 0; mi < 4; ++mi) {
                int row = wm * 64 + mi * 16 + (lane & 15);
                ldmx4(afr[mi], st + (((row << 3) + (cA ^ (row & 7))) << 4));
            }
#pragma unroll
            for (int mi = 0; mi < 4; ++mi)
#pragma unroll
                for (int ni = 0; ni < 4; ++ni)
                    mma16816(acc[mi][ni], afr[mi], bfr[ni]);
            // lo pass (reuse afr)
#pragma unroll
            for (int mi = 0; mi < 4; ++mi) {
                int row = wm * 64 + mi * 16 + (lane & 15);
                ldmx4(afr[mi], st + MAT_BYTES + (((row << 3) + (cA ^ (row & 7))) << 4));
            }
#pragma unroll
            for (int mi = 0; mi < 4; ++mi)
#pragma unroll
                for (int ni = 0; ni < 4; ++ni)
                    mma16816(acc[mi][ni], afr[mi], bfr[ni]);
        }

        __syncthreads();
        int nk = kt + 2;
        if (nk < KT) { load_stage(nk & 1, nk); CP_COMMIT(); }
    }

    // epilogue
    const int gro = lane >> 2, t4 = lane & 3;
    const int colb = n0 + wn * 32 + t4 * 2;
#pragma unroll
    for (int mi = 0; mi < 4; ++mi) {
#pragma unroll
        for (int half = 0; half < 2; ++half) {
            int r = m0 + wm * 64 + mi * 16 + gro + half * 8;
            float* crow = C + (size_t)r * N;
#pragma unroll
            for (int ni = 0; ni < 4; ++ni) {
                int col = colb + ni * 8;
                float x = acc[mi][ni][half * 2 + 0];
                float y = acc[mi][ni][half * 2 + 1];
                if (MODE == 2) {
                    atomicAdd(crow + col, x);       // RED.ADD (return unused)
                    atomicAdd(crow + col + 1, y);
                } else {
                    x += bias[col];
                    y += bias[col + 1];
                    if (MODE == 1) { x = fmaxf(x, 0.f); y = fmaxf(y, 0.f); }
                    *(float2*)(crow + col) = make_float2(x, y);
                }
            }
        }
    }
}

// ---------------- BN stats (deterministic split-K) ----------------
__global__ __launch_bounds__(256) void colstats_partial(
    const float* __restrict__ X, int N, int rowsPerBlk)
{
    const int c = blockIdx.x * blockDim.x + threadIdx.x;
    const int r0 = blockIdx.y * rowsPerBlk;
    float s = 0.f, q = 0.f;
    for (int r = r0; r < r0 + rowsPerBlk; ++r) {
        float v = X[(size_t)r * N + c];
        s += v; q = fmaf(v, v, q);
    }
    g_psum[blockIdx.y * N + c] = s;
    g_psq [blockIdx.y * N + c] = q;
}
__global__ __launch_bounds__(256) void colstats_final(
    const float* __restrict__ g, const float* __restrict__ beta, int N, float invM)
{
    const int c = blockIdx.x * blockDim.x + threadIdx.x;
    float s = 0.f, q = 0.f;
#pragma unroll 4
    for (int i = 0; i < SPLITS; ++i) { s += g_psum[i * N + c]; q += g_psq[i * N + c]; }
    float m = s * invM;
    float v = q * invM - m * m;
    float sc = g[c] * rsqrtf(v + EPSBN);
    g_scale[c] = sc;
    g_shift[c] = beta[c] - m * sc;
}

// ---------------- launch ----------------
extern "C" void kernel_launch(void* const* d_in, const int* in_sizes, int n_in,
                              void* d_out, int out_size)
{
    const float* ft0   = (const float*)d_in[1];
    const float* ft1   = (const float*)d_in[2];
    const float* ft2   = (const float*)d_in[3];
    const float* key   = (const float*)d_in[4];
    const float* W1    = (const float*)d_in[5];
    const float* g1    = (const float*)d_in[7];
    const float* beta1 = (const float*)d_in[8];
    const float* W2    = (const float*)d_in[9];
    const float* g2    = (const float*)d_in[11];
    const float* beta2 = (const float*)d_in[12];
    const float* W3    = (const float*)d_in[13];
    const float* b3    = (const float*)d_in[14];
    const float* We    = (const float*)d_in[15];
    const float* bE    = (const float*)d_in[16];

    float* out     = (float*)d_out;
    float* aligned = out;
    float* extend  = aligned + (size_t)BATCH * CH_H;
    float* ftall   = extend  + (size_t)BATCH * DIM;

    float* buf0;
    __half *Ah, *Al, *Bh;
    cudaGetSymbolAddress((void**)&buf0, g_buf0);
    cudaGetSymbolAddress((void**)&Ah, g_Ah);
    cudaGetSymbolAddress((void**)&Al, g_Al);
    cudaGetSymbolAddress((void**)&Bh, g_Bh);

    cudaFuncSetAttribute(gemm_mma<1>, cudaFuncAttributeMaxDynamicSharedMemorySize, SMEM_GEMM);
    cudaFuncSetAttribute(gemm_mma<2>, cudaFuncAttributeMaxDynamicSharedMemorySize, SMEM_GEMM);

    const int MT = BATCH / BM;                    // 64
    const int ZB = BATCH * CH_H / 4 / 256;        // zero-init blocks (16384)
    const int PB = BATCH * CH_H / 8 / 256;        // pack blocks

    // 1) score + reweight + pack A1
    score_pack<<<BATCH, 512>>>(ft0, ft1, ft2, key, ftall, Ah, Al);

    // 2) layer 1: y1 = ftall @ W1   (bias cancels in BN), split-K=2
    pack_W_t<<<dim3(DIM / 32, CH_H / 32), 256>>>(W1, Bh, DIM, CH_H);
    zero_kernel<<<ZB, 256>>>((float4*)buf0);
    gemm_mma<2><<<dim3(CH_H / BN, MT, 2), 256, SMEM_GEMM>>>(Ah, Al, Bh, nullptr, buf0,
                                                            CH_H, DIM, DIM / 2);
    colstats_partial<<<dim3(CH_H / 256, SPLITS), 256>>>(buf0, CH_H, BATCH / SPLITS);
    colstats_final<<<CH_H / 256, 256>>>(g1, beta1, CH_H, 1.0f / BATCH);
    bn_pack<<<PB, 256>>>(buf0, Ah, Al, CH_H);

    // 3) layer 2: split-K=2, bias cancels in BN
    pack_W_t<<<dim3(CH_H / 32, CH_H / 32), 256>>>(W2, Bh, CH_H, CH_H);
    zero_kernel<<<ZB, 256>>>((float4*)buf0);
    gemm_mma<2><<<dim3(CH_H / BN, MT, 2), 256, SMEM_GEMM>>>(Ah, Al, Bh, nullptr, buf0,
                                                            CH_H, CH_H, CH_H / 2);
    colstats_partial<<<dim3(CH_H / 256, SPLITS), 256>>>(buf0, CH_H, BATCH / SPLITS);
    colstats_final<<<CH_H / 256, 256>>>(g2, beta2, CH_H, 1.0f / BATCH);
    bn_pack<<<PB, 256>>>(buf0, Ah, Al, CH_H);

    // 4) layer 3: split-K=2 into zeroed 'aligned', then fused bias+relu+pack
    pack_W_t<<<dim3(CH_H / 32, CH_H / 32), 256>>>(W3, Bh, CH_H, CH_H);
    zero_kernel<<<ZB, 256>>>((float4*)aligned);
    gemm_mma<2><<<dim3(CH_H / BN, MT, 2), 256, SMEM_GEMM>>>(Ah, Al, Bh, nullptr, aligned,
                                                            CH_H, CH_H, CH_H / 2);
    bias_relu_pack<<<PB, 256>>>(aligned, b3, Ah, Al);

    // 5) extend = relu(aligned @ We + bE)  (3072 CTAs, plain epilogue)
    pack_W_t<<<dim3(CH_H / 32, DIM / 32), 256>>>(We, Bh, CH_H, DIM);
    gemm_mma<1><<<dim3(DIM / BN, MT), 256, SMEM_GEMM>>>(Ah, Al, Bh, bE, extend,
                                                        DIM, CH_H, CH_H);
}

// round 8
// speedup vs baseline: 1.0334x; 1.0334x over previous
#include <cuda_runtime.h>
#include <cuda_fp16.h>
#include <cstdint>

// Problem dims
#define BATCH   8192
#define CH_H    2048
#define DIM     6144
#define CHUNK   512
#define NCHUNK  12
#define EPSBN   1e-5f
#define SPLITS  64

// GEMM tiling (128x128 tile, 2-stage, 2 CTAs/SM)
#define BM 128
#define BN 128
#define STAGES 2
#define MAT_BYTES 16384              // 128 rows x 128 B (64 fp16)
#define STAGE_BYTES (3 * MAT_BYTES)  // Ah, Al, Bh = 49152
#define SMEM_GEMM (STAGES * STAGE_BYTES)   // 98304 -> 2 CTAs/SM

// ---------------- scratch ----------------
__device__ float g_buf0[(size_t)BATCH * CH_H];
__device__ float g_psum[SPLITS * CH_H];
__device__ float g_psq [SPLITS * CH_H];
__device__ float g_scale[CH_H];
__device__ float g_shift[CH_H];
__device__ __half g_Ah[(size_t)BATCH * DIM];
__device__ __half g_Al[(size_t)BATCH * DIM];
__device__ __half g_Bh[(size_t)DIM * CH_H];

// ---------------- helpers ----------------
__device__ __forceinline__ uint32_t smem_u32(const void* p) {
    uint32_t a;
    asm("{ .reg .u64 t; cvta.to.shared.u64 t, %1; cvt.u32.u64 %0, t; }" : "=r"(a) : "l"(p));
    return a;
}
__device__ __forceinline__ void cp16(uint32_t s, const void* g) {
    asm volatile("cp.async.cg.shared.global [%0], [%1], 16;" :: "r"(s), "l"(g));
}
#define CP_COMMIT() asm volatile("cp.async.commit_group;" ::: "memory")
#define CP_WAIT1()  asm volatile("cp.async.wait_group 1;" ::: "memory")

__device__ __forceinline__ void ldmx4(uint32_t* r, uint32_t addr) {
    asm volatile("ldmatrix.sync.aligned.m8n8.x4.shared.b16 {%0,%1,%2,%3}, [%4];"
                 : "=r"(r[0]), "=r"(r[1]), "=r"(r[2]), "=r"(r[3]) : "r"(addr));
}
__device__ __forceinline__ void mma16816(float* d, const uint32_t* a, const uint32_t* b) {
    asm volatile("mma.sync.aligned.m16n8k16.row.col.f32.f16.f16.f32 "
                 "{%0,%1,%2,%3}, {%4,%5,%6,%7}, {%8,%9}, {%0,%1,%2,%3};"
                 : "+f"(d[0]), "+f"(d[1]), "+f"(d[2]), "+f"(d[3])
                 : "r"(a[0]), "r"(a[1]), "r"(a[2]), "r"(a[3]), "r"(b[0]), "r"(b[1]));
}
__device__ __forceinline__ void split2h(float f0, float f1, uint32_t& hp, uint32_t& lp) {
    __half h0 = __float2half_rn(f0);
    __half h1 = __float2half_rn(f1);
    __half l0 = __float2half_rn(f0 - __half2float(h0));
    __half l1 = __float2half_rn(f1 - __half2float(h1));
    hp = (uint32_t)__half_as_ushort(h0) | ((uint32_t)__half_as_ushort(h1) << 16);
    lp = (uint32_t)__half_as_ushort(l0) | ((uint32_t)__half_as_ushort(l1) << 16);
}
__device__ __forceinline__ uint32_t pack2h(float f0, float f1) {
    __half h0 = __float2half_rn(f0);
    __half h1 = __float2half_rn(f1);
    return (uint32_t)__half_as_ushort(h0) | ((uint32_t)__half_as_ushort(h1) << 16);
}

// ---------------- score + reweight + pack A (layer-1 input) ----------------
__global__ __launch_bounds__(512) void score_pack(
    const float* __restrict__ ft0, const float* __restrict__ ft1,
    const float* __restrict__ ft2, const float* __restrict__ key,
    float* __restrict__ ft_all, __half* __restrict__ Ah, __half* __restrict__ Al)
{
    const int row = blockIdx.x, t = threadIdx.x;
    const int warp = t >> 5, lane = t & 31;
    __shared__ float wsum[16];
    __shared__ float sc[NCHUNK];
    const float kv = key[t];
    float x[NCHUNK];
#pragma unroll
    for (int c = 0; c < NCHUNK; ++c) {
        const float* src = (c < 4) ? ft0 : ((c < 8) ? ft1 : ft2);
        x[c] = src[(size_t)row * CH_H + (c & 3) * CHUNK + t];
    }
#pragma unroll
    for (int c = 0; c < NCHUNK; ++c) {
        float p = x[c] * kv;
#pragma unroll
        for (int o = 16; o; o >>= 1) p += __shfl_xor_sync(0xffffffffu, p, o);
        if (lane == 0) wsum[warp] = p;
        __syncthreads();
        if (warp == 0) {
            float q = (lane < 16) ? wsum[lane] : 0.f;
#pragma unroll
            for (int o = 8; o; o >>= 1) q += __shfl_xor_sync(0xffffffffu, q, o);
            if (lane == 0) sc[c] = q;
        }
        __syncthreads();
    }
    float mx = sc[0];
#pragma unroll
    for (int c = 1; c < NCHUNK; ++c) mx = fmaxf(mx, sc[c]);
    float e[NCHUNK], s = 0.f;
#pragma unroll
    for (int c = 0; c < NCHUNK; ++c) { e[c] = expf(sc[c] - mx); s += e[c]; }
    const float inv = 1.0f / s;
#pragma unroll
    for (int c = 0; c < NCHUNK; ++c) {
        float v = x[c] * (1.0f + e[c] * inv);
        size_t idx = (size_t)row * DIM + c * CHUNK + t;
        ft_all[idx] = v;
        __half h = __float2half_rn(v);
        Ah[idx] = h;
        Al[idx] = __float2half_rn(v - __half2float(h));
    }
}

// ---------------- pack A from fp32 row-major (layer-4 input) ----------------
__global__ __launch_bounds__(256) void pack_A_rm(
    const float* __restrict__ X, __half* __restrict__ Ah, __half* __restrict__ Al)
{
    size_t i = ((size_t)blockIdx.x * 256 + threadIdx.x) * 8;
    float4 v0 = *(const float4*)(X + i);
    float4 v1 = *(const float4*)(X + i + 4);
    uint4 hp, lp;
    split2h(v0.x, v0.y, hp.x, lp.x);
    split2h(v0.z, v0.w, hp.y, lp.y);
    split2h(v1.x, v1.y, hp.z, lp.z);
    split2h(v1.z, v1.w, hp.w, lp.w);
    *(uint4*)((char*)Ah + i * 2) = hp;
    *(uint4*)((char*)Al + i * 2) = lp;
}

// ---------------- BN apply fused with A-pack ----------------
__global__ __launch_bounds__(256) void bn_pack(
    const float* __restrict__ Y, __half* __restrict__ Ah,
    __half* __restrict__ Al, int K)
{
    size_t i = ((size_t)blockIdx.x * 256 + threadIdx.x) * 8;
    int col = (int)(i % K);
    float4 y0 = *(const float4*)(Y + i);
    float4 y1 = *(const float4*)(Y + i + 4);
    float4 s0 = *(const float4*)(g_scale + col);
    float4 s1 = *(const float4*)(g_scale + col + 4);
    float4 h0 = *(const float4*)(g_shift + col);
    float4 h1 = *(const float4*)(g_shift + col + 4);
    float f[8] = {
        fmaf(y0.x, s0.x, h0.x), fmaf(y0.y, s0.y, h0.y),
        fmaf(y0.z, s0.z, h0.z), fmaf(y0.w, s0.w, h0.w),
        fmaf(y1.x, s1.x, h1.x), fmaf(y1.y, s1.y, h1.y),
        fmaf(y1.z, s1.z, h1.z), fmaf(y1.w, s1.w, h1.w)};
    uint4 hp, lp;
    split2h(f[0], f[1], hp.x, lp.x);
    split2h(f[2], f[3], hp.y, lp.y);
    split2h(f[4], f[5], hp.z, lp.z);
    split2h(f[6], f[7], hp.w, lp.w);
    *(uint4*)((char*)Ah + i * 2) = hp;
    *(uint4*)((char*)Al + i * 2) = lp;
}

// ---------------- pack W: fp32 [K,N] -> fp16 [N,K] (transpose) ----------
__global__ __launch_bounds__(256) void pack_W_t(
    const float* __restrict__ W, __half* __restrict__ Bh, int K, int N)
{
    __shared__ float sm[32][33];
    const int k0 = blockIdx.x * 32, n0 = blockIdx.y * 32;
    const int tx = threadIdx.x & 31, ty = threadIdx.x >> 5;
#pragma unroll
    for (int i = 0; i < 4; ++i)
        sm[ty + 8 * i][tx] = W[(size_t)(k0 + ty + 8 * i) * N + n0 + tx];
    __syncthreads();
    const int kp = threadIdx.x & 15;
    const int nb = threadIdx.x >> 4;
#pragma unroll
    for (int j = 0; j < 2; ++j) {
        int n = nb + j * 16;
        *(uint32_t*)&Bh[(size_t)(n0 + n) * K + k0 + kp * 2] =
            pack2h(sm[kp * 2][n], sm[kp * 2 + 1][n]);
    }
}

// ---------------- mma.sync GEMM: C = A@B^T + bias (opt ReLU), fp16 2-pass ------
// CTA 128x128, warp tile 64x32 (2x4 warps), 2-stage, 2 CTAs/SM.
// All 12 ldmatrix per kk issued up-front (separate hi/lo regs) to keep HMMA dense.
template <int RELU>
__global__ __launch_bounds__(256, 2) void gemm_mma(
    const __half* __restrict__ Ah, const __half* __restrict__ Al,
    const __half* __restrict__ Bh,
    const float* __restrict__ bias, float* __restrict__ C, int N, int K)
{
    extern __shared__ __align__(128) char smem[];
    const uint32_t sb = smem_u32(smem);
    const int tid = threadIdx.x, lane = tid & 31, wid = tid >> 5;
    const int wm = wid & 1, wn = wid >> 1;
    const int m0 = blockIdx.y * BM, n0 = blockIdx.x * BN;
    const int KT = K >> 6;

    const __half* g0 = Ah + (size_t)m0 * K;
    const __half* g1 = Al + (size_t)m0 * K;
    const __half* g2 = Bh + (size_t)n0 * K;

    float acc[4][4][4];
#pragma unroll
    for (int a = 0; a < 4; ++a)
#pragma unroll
        for (int b = 0; b < 4; ++b)
#pragma unroll
            for (int c = 0; c < 4; ++c) acc[a][b][c] = 0.f;

    auto load_stage = [&](int slot, int kt) {
        const uint32_t st = sb + slot * STAGE_BYTES;
        const int k0 = kt << 6;
        const __half* gs[3] = {g0, g1, g2};
#pragma unroll
        for (int mtx = 0; mtx < 3; ++mtx) {
            const uint32_t base = st + mtx * MAT_BYTES;
            const __half* g = gs[mtx];
#pragma unroll
            for (int i = 0; i < 4; ++i) {
                int q = tid + i * 256;
                int row = q >> 3, c = q & 7;
                uint32_t sa = base + (((row << 3) + (c ^ (row & 7))) << 4);
                cp16(sa, g + (size_t)row * K + k0 + c * 8);
            }
        }
    };

    load_stage(0, 0); CP_COMMIT();
    load_stage(1, 1); CP_COMMIT();

    for (int kt = 0; kt < KT; ++kt) {
        CP_WAIT1();              // stage kt resident (kt+1 may be in flight)
        __syncthreads();

        const uint32_t st = sb + (kt & 1) * STAGE_BYTES;
#pragma unroll
        for (int kk = 0; kk < 4; ++kk) {
            const int cA = (kk << 1) + (lane >> 4);
            uint32_t bfr[4][2], afh[4][4], afl[4][4];
            // issue ALL fragment loads up-front: B, A-hi, A-lo
#pragma unroll
            for (int half = 0; half < 2; ++half) {
                int row = wn * 32 + half * 16 + (lane & 15);
                uint32_t ad = st + 2 * MAT_BYTES + (((row << 3) + (cA ^ (row & 7))) << 4);
                uint32_t r[4];
                ldmx4(r, ad);
                bfr[half * 2][0] = r[0]; bfr[half * 2][1] = r[2];
                bfr[half * 2 + 1][0] = r[1]; bfr[half * 2 + 1][1] = r[3];
            }
#pragma unroll
            for (int mi = 0; mi < 4; ++mi) {
                int row = wm * 64 + mi * 16 + (lane & 15);
                uint32_t off = (((row << 3) + (cA ^ (row & 7))) << 4);
                ldmx4(afh[mi], st + off);
                ldmx4(afl[mi], st + MAT_BYTES + off);
            }
            // dense HMMA: hi pass then lo pass, no interleaved loads
#pragma unroll
            for (int mi = 0; mi < 4; ++mi)
#pragma unroll
                for (int ni = 0; ni < 4; ++ni)
                    mma16816(acc[mi][ni], afh[mi], bfr[ni]);
#pragma unroll
            for (int mi = 0; mi < 4; ++mi)
#pragma unroll
                for (int ni = 0; ni < 4; ++ni)
                    mma16816(acc[mi][ni], afl[mi], bfr[ni]);
        }

        __syncthreads();         // all warps done with slot kt&1
        int nk = kt + 2;
        if (nk < KT) { load_stage(nk & 1, nk); CP_COMMIT(); }
    }

    // epilogue
    const int gro = lane >> 2, t4 = lane & 3;
    const int colb = n0 + wn * 32 + t4 * 2;
#pragma unroll
    for (int mi = 0; mi < 4; ++mi) {
#pragma unroll
        for (int half = 0; half < 2; ++half) {
            int r = m0 + wm * 64 + mi * 16 + gro + half * 8;
            float* crow = C + (size_t)r * N;
#pragma unroll
            for (int ni = 0; ni < 4; ++ni) {
                int col = colb + ni * 8;
                float x = acc[mi][ni][half * 2 + 0] + bias[col];
                float y = acc[mi][ni][half * 2 + 1] + bias[col + 1];
                if (RELU) { x = fmaxf(x, 0.f); y = fmaxf(y, 0.f); }
                *(float2*)(crow + col) = make_float2(x, y);
            }
        }
    }
}

// ---------------- BN stats (deterministic split-K) ----------------
__global__ __launch_bounds__(256) void colstats_partial(
    const float* __restrict__ X, int N, int rowsPerBlk)
{
    const int c = blockIdx.x * blockDim.x + threadIdx.x;
    const int r0 = blockIdx.y * rowsPerBlk;
    float s = 0.f, q = 0.f;
    for (int r = r0; r < r0 + rowsPerBlk; ++r) {
        float v = X[(size_t)r * N + c];
        s += v; q = fmaf(v, v, q);
    }
    g_psum[blockIdx.y * N + c] = s;
    g_psq [blockIdx.y * N + c] = q;
}
__global__ __launch_bounds__(256) void colstats_final(
    const float* __restrict__ g, const float* __restrict__ beta, int N, float invM)
{
    const int c = blockIdx.x * blockDim.x + threadIdx.x;
    float s = 0.f, q = 0.f;
#pragma unroll 4
    for (int i = 0; i < SPLITS; ++i) { s += g_psum[i * N + c]; q += g_psq[i * N + c]; }
    float m = s * invM;
    float v = q * invM - m * m;
    float sc = g[c] * rsqrtf(v + EPSBN);
    g_scale[c] = sc;
    g_shift[c] = beta[c] - m * sc;
}

// ---------------- launch ----------------
extern "C" void kernel_launch(void* const* d_in, const int* in_sizes, int n_in,
                              void* d_out, int out_size)
{
    const float* ft0   = (const float*)d_in[1];
    const float* ft1   = (const float*)d_in[2];
    const float* ft2   = (const float*)d_in[3];
    const float* key   = (const float*)d_in[4];
    const float* W1    = (const float*)d_in[5];
    const float* b1    = (const float*)d_in[6];
    const float* g1    = (const float*)d_in[7];
    const float* beta1 = (const float*)d_in[8];
    const float* W2    = (const float*)d_in[9];
    const float* b2    = (const float*)d_in[10];
    const float* g2    = (const float*)d_in[11];
    const float* beta2 = (const float*)d_in[12];
    const float* W3    = (const float*)d_in[13];
    const float* b3    = (const float*)d_in[14];
    const float* We    = (const float*)d_in[15];
    const float* bE    = (const float*)d_in[16];

    float* out     = (float*)d_out;
    float* aligned = out;
    float* extend  = aligned + (size_t)BATCH * CH_H;
    float* ftall   = extend  + (size_t)BATCH * DIM;

    float* buf0;
    __half *Ah, *Al, *Bh;
    cudaGetSymbolAddress((void**)&buf0, g_buf0);
    cudaGetSymbolAddress((void**)&Ah, g_Ah);
    cudaGetSymbolAddress((void**)&Al, g_Al);
    cudaGetSymbolAddress((void**)&Bh, g_Bh);

    cudaFuncSetAttribute(gemm_mma<0>, cudaFuncAttributeMaxDynamicSharedMemorySize, SMEM_GEMM);
    cudaFuncSetAttribute(gemm_mma<1>, cudaFuncAttributeMaxDynamicSharedMemorySize, SMEM_GEMM);

    const int MT = BATCH / BM;  // 64

    // 1) score + reweight + pack A1
    score_pack<<<BATCH, 512>>>(ft0, ft1, ft2, key, ftall, Ah, Al);

    // 2) layer 1: y1 = ftall @ W1 + b1  (K = 6144)
    pack_W_t<<<dim3(DIM / 32, CH_H / 32), 256>>>(W1, Bh, DIM, CH_H);
    gemm_mma<0><<<dim3(CH_H / BN, MT), 256, SMEM_GEMM>>>(Ah, Al, Bh, b1, buf0,
                                                         CH_H, DIM);
    colstats_partial<<<dim3(CH_H / 256, SPLITS), 256>>>(buf0, CH_H, BATCH / SPLITS);
    colstats_final<<<CH_H / 256, 256>>>(g1, beta1, CH_H, 1.0f / BATCH);
    bn_pack<<<BATCH * CH_H / 8 / 256, 256>>>(buf0, Ah, Al, CH_H);

    // 3) layer 2 (K = 2048)
    pack_W_t<<<dim3(CH_H / 32, CH_H / 32), 256>>>(W2, Bh, CH_H, CH_H);
    gemm_mma<0><<<dim3(CH_H / BN, MT), 256, SMEM_GEMM>>>(Ah, Al, Bh, b2, buf0,
                                                         CH_H, CH_H);
    colstats_partial<<<dim3(CH_H / 256, SPLITS), 256>>>(buf0, CH_H, BATCH / SPLITS);
    colstats_final<<<CH_H / 256, 256>>>(g2, beta2, CH_H, 1.0f / BATCH);
    bn_pack<<<BATCH * CH_H / 8 / 256, 256>>>(buf0, Ah, Al, CH_H);

    // 4) layer 3: aligned = relu(h2 @ W3 + b3)
    pack_W_t<<<dim3(CH_H / 32, CH_H / 32), 256>>>(W3, Bh, CH_H, CH_H);
    gemm_mma<1><<<dim3(CH_H / BN, MT), 256, SMEM_GEMM>>>(Ah, Al, Bh, b3, aligned,
                                                         CH_H, CH_H);

    // 5) extend = relu(aligned @ We + bE)
    pack_A_rm<<<BATCH * CH_H / 8 / 256, 256>>>(aligned, Ah, Al);
    pack_W_t<<<dim3(CH_H / 32, DIM / 32), 256>>>(We, Bh, CH_H, DIM);
    gemm_mma<1><<<dim3(DIM / BN, MT), 256, SMEM_GEMM>>>(Ah, Al, Bh, bE, extend,
                                                        DIM, CH_H);
}

// round 9
// speedup vs baseline: 1.7216x; 1.6660x over previous
#include <cuda_runtime.h>
#include <cuda_fp16.h>
#include <cstdint>

// Problem dims
#define BATCH   8192
#define CH_H    2048
#define DIM     6144
#define CHUNK   512
#define NCHUNK  12
#define EPSBN   1e-5f
#define SPLITS  64

// GEMM tiling (128x128 tile, 3-stage, 2 CTAs/SM, single-pass fp16)
#define BM 128
#define BN 128
#define STAGES 3
#define MAT_BYTES 16384              // 128 rows x 128 B (64 fp16)
#define STAGE_BYTES (2 * MAT_BYTES)  // Ah, Bh = 32768
#define SMEM_GEMM (STAGES * STAGE_BYTES)   // 98304 -> 2 CTAs/SM

// ---------------- scratch ----------------
__device__ float g_buf0[(size_t)BATCH * CH_H];
__device__ float g_psum[SPLITS * CH_H];
__device__ float g_psq [SPLITS * CH_H];
__device__ float g_scale[CH_H];
__device__ float g_shift[CH_H];
__device__ __half g_Ah[(size_t)BATCH * DIM];
__device__ __half g_Bh[(size_t)DIM * CH_H];

// ---------------- helpers ----------------
__device__ __forceinline__ uint32_t smem_u32(const void* p) {
    uint32_t a;
    asm("{ .reg .u64 t; cvta.to.shared.u64 t, %1; cvt.u32.u64 %0, t; }" : "=r"(a) : "l"(p));
    return a;
}
__device__ __forceinline__ void cp16(uint32_t s, const void* g) {
    asm volatile("cp.async.cg.shared.global [%0], [%1], 16;" :: "r"(s), "l"(g));
}
#define CP_COMMIT() asm volatile("cp.async.commit_group;" ::: "memory")
#define CP_WAIT1()  asm volatile("cp.async.wait_group 1;" ::: "memory")

__device__ __forceinline__ void ldmx4(uint32_t* r, uint32_t addr) {
    asm volatile("ldmatrix.sync.aligned.m8n8.x4.shared.b16 {%0,%1,%2,%3}, [%4];"
                 : "=r"(r[0]), "=r"(r[1]), "=r"(r[2]), "=r"(r[3]) : "r"(addr));
}
__device__ __forceinline__ void mma16816(float* d, const uint32_t* a, const uint32_t* b) {
    asm volatile("mma.sync.aligned.m16n8k16.row.col.f32.f16.f16.f32 "
                 "{%0,%1,%2,%3}, {%4,%5,%6,%7}, {%8,%9}, {%0,%1,%2,%3};"
                 : "+f"(d[0]), "+f"(d[1]), "+f"(d[2]), "+f"(d[3])
                 : "r"(a[0]), "r"(a[1]), "r"(a[2]), "r"(a[3]), "r"(b[0]), "r"(b[1]));
}
__device__ __forceinline__ uint32_t pack2h(float f0, float f1) {
    __half h0 = __float2half_rn(f0);
    __half h1 = __float2half_rn(f1);
    return (uint32_t)__half_as_ushort(h0) | ((uint32_t)__half_as_ushort(h1) << 16);
}

// ---------------- score + reweight + pack A (layer-1 input) ----------------
__global__ __launch_bounds__(512) void score_pack(
    const float* __restrict__ ft0, const float* __restrict__ ft1,
    const float* __restrict__ ft2, const float* __restrict__ key,
    float* __restrict__ ft_all, __half* __restrict__ Ah)
{
    const int row = blockIdx.x, t = threadIdx.x;
    const int warp = t >> 5, lane = t & 31;
    __shared__ float wsum[16];
    __shared__ float sc[NCHUNK];
    const float kv = key[t];
    float x[NCHUNK];
#pragma unroll
    for (int c = 0; c < NCHUNK; ++c) {
        const float* src = (c < 4) ? ft0 : ((c < 8) ? ft1 : ft2);
        x[c] = src[(size_t)row * CH_H + (c & 3) * CHUNK + t];
    }
#pragma unroll
    for (int c = 0; c < NCHUNK; ++c) {
        float p = x[c] * kv;
#pragma unroll
        for (int o = 16; o; o >>= 1) p += __shfl_xor_sync(0xffffffffu, p, o);
        if (lane == 0) wsum[warp] = p;
        __syncthreads();
        if (warp == 0) {
            float q = (lane < 16) ? wsum[lane] : 0.f;
#pragma unroll
            for (int o = 8; o; o >>= 1) q += __shfl_xor_sync(0xffffffffu, q, o);
            if (lane == 0) sc[c] = q;
        }
        __syncthreads();
    }
    float mx = sc[0];
#pragma unroll
    for (int c = 1; c < NCHUNK; ++c) mx = fmaxf(mx, sc[c]);
    float e[NCHUNK], s = 0.f;
#pragma unroll
    for (int c = 0; c < NCHUNK; ++c) { e[c] = expf(sc[c] - mx); s += e[c]; }
    const float inv = 1.0f / s;
#pragma unroll
    for (int c = 0; c < NCHUNK; ++c) {
        float v = x[c] * (1.0f + e[c] * inv);
        size_t idx = (size_t)row * DIM + c * CHUNK + t;
        ft_all[idx] = v;
        Ah[idx] = __float2half_rn(v);
    }
}

// ---------------- pack A from fp32 row-major (layer-4 input) ----------------
__global__ __launch_bounds__(256) void pack_A_rm(
    const float* __restrict__ X, __half* __restrict__ Ah)
{
    size_t i = ((size_t)blockIdx.x * 256 + threadIdx.x) * 8;
    float4 v0 = *(const float4*)(X + i);
    float4 v1 = *(const float4*)(X + i + 4);
    uint4 hp;
    hp.x = pack2h(v0.x, v0.y);
    hp.y = pack2h(v0.z, v0.w);
    hp.z = pack2h(v1.x, v1.y);
    hp.w = pack2h(v1.z, v1.w);
    *(uint4*)((char*)Ah + i * 2) = hp;
}

// ---------------- BN apply fused with A-pack ----------------
__global__ __launch_bounds__(256) void bn_pack(
    const float* __restrict__ Y, __half* __restrict__ Ah, int K)
{
    size_t i = ((size_t)blockIdx.x * 256 + threadIdx.x) * 8;
    int col = (int)(i % K);
    float4 y0 = *(const float4*)(Y + i);
    float4 y1 = *(const float4*)(Y + i + 4);
    float4 s0 = *(const float4*)(g_scale + col);
    float4 s1 = *(const float4*)(g_scale + col + 4);
    float4 h0 = *(const float4*)(g_shift + col);
    float4 h1 = *(const float4*)(g_shift + col + 4);
    uint4 hp;
    hp.x = pack2h(fmaf(y0.x, s0.x, h0.x), fmaf(y0.y, s0.y, h0.y));
    hp.y = pack2h(fmaf(y0.z, s0.z, h0.z), fmaf(y0.w, s0.w, h0.w));
    hp.z = pack2h(fmaf(y1.x, s1.x, h1.x), fmaf(y1.y, s1.y, h1.y));
    hp.w = pack2h(fmaf(y1.z, s1.z, h1.z), fmaf(y1.w, s1.w, h1.w));
    *(uint4*)((char*)Ah + i * 2) = hp;
}

// ---------------- pack W: fp32 [K,N] -> fp16 [N,K] (transpose) ----------
__global__ __launch_bounds__(256) void pack_W_t(
    const float* __restrict__ W, __half* __restrict__ Bh, int K, int N)
{
    __shared__ float sm[32][33];
    const int k0 = blockIdx.x * 32, n0 = blockIdx.y * 32;
    const int tx = threadIdx.x & 31, ty = threadIdx.x >> 5;
#pragma unroll
    for (int i = 0; i < 4; ++i)
        sm[ty + 8 * i][tx] = W[(size_t)(k0 + ty + 8 * i) * N + n0 + tx];
    __syncthreads();
    const int kp = threadIdx.x & 15;
    const int nb = threadIdx.x >> 4;
#pragma unroll
    for (int j = 0; j < 2; ++j) {
        int n = nb + j * 16;
        *(uint32_t*)&Bh[(size_t)(n0 + n) * K + k0 + kp * 2] =
            pack2h(sm[kp * 2][n], sm[kp * 2 + 1][n]);
    }
}

// ---------------- mma.sync GEMM: C = A@B^T + bias (opt ReLU), fp16 1-pass ------
// CTA 128x128, warp tile 64x32 (2x4 warps), 3-stage, 2 CTAs/SM, 1 sync per tile.
template <int RELU>
__global__ __launch_bounds__(256, 2) void gemm_mma(
    const __half* __restrict__ Ah, const __half* __restrict__ Bh,
    const float* __restrict__ bias, float* __restrict__ C, int N, int K)
{
    extern __shared__ __align__(128) char smem[];
    const uint32_t sb = smem_u32(smem);
    const int tid = threadIdx.x, lane = tid & 31, wid = tid >> 5;
    const int wm = wid & 1, wn = wid >> 1;
    const int m0 = blockIdx.y * BM, n0 = blockIdx.x * BN;
    const int KT = K >> 6;

    const __half* g0 = Ah + (size_t)m0 * K;
    const __half* g1 = Bh + (size_t)n0 * K;

    float acc[4][4][4];
#pragma unroll
    for (int a = 0; a < 4; ++a)
#pragma unroll
        for (int b = 0; b < 4; ++b)
#pragma unroll
            for (int c = 0; c < 4; ++c) acc[a][b][c] = 0.f;

    auto load_stage = [&](int slot, int kt) {
        const uint32_t st = sb + slot * STAGE_BYTES;
        const int k0 = kt << 6;
        const __half* gs[2] = {g0, g1};
#pragma unroll
        for (int mtx = 0; mtx < 2; ++mtx) {
            const uint32_t base = st + mtx * MAT_BYTES;
            const __half* g = gs[mtx];
#pragma unroll
            for (int i = 0; i < 4; ++i) {
                int q = tid + i * 256;
                int row = q >> 3, c = q & 7;
                uint32_t sa = base + (((row << 3) + (c ^ (row & 7))) << 4);
                cp16(sa, g + (size_t)row * K + k0 + c * 8);
            }
        }
    };

    load_stage(0, 0); CP_COMMIT();
    load_stage(1, 1); CP_COMMIT();

    int slot = 0;
    for (int kt = 0; kt < KT; ++kt) {
        CP_WAIT1();              // stage kt resident (kt+1 may be in flight)
        __syncthreads();         // also fences prior iteration's readers of slot+2

        int nk = kt + 2;
        if (nk < KT) {
            int ns = slot + 2; if (ns >= STAGES) ns -= STAGES;
            load_stage(ns, nk);  // disjoint from compute slot and in-flight slot
            CP_COMMIT();
        }

        const uint32_t st = sb + slot * STAGE_BYTES;
#pragma unroll
        for (int kk = 0; kk < 4; ++kk) {
            const int cA = (kk << 1) + (lane >> 4);
            uint32_t bfr[4][2], afr[4][4];
#pragma unroll
            for (int half = 0; half < 2; ++half) {
                int row = wn * 32 + half * 16 + (lane & 15);
                uint32_t ad = st + MAT_BYTES + (((row << 3) + (cA ^ (row & 7))) << 4);
                uint32_t r[4];
                ldmx4(r, ad);
                bfr[half * 2][0] = r[0]; bfr[half * 2][1] = r[2];
                bfr[half * 2 + 1][0] = r[1]; bfr[half * 2 + 1][1] = r[3];
            }
#pragma unroll
            for (int mi = 0; mi < 4; ++mi) {
                int row = wm * 64 + mi * 16 + (lane & 15);
                ldmx4(afr[mi], st + (((row << 3) + (cA ^ (row & 7))) << 4));
            }
#pragma unroll
            for (int mi = 0; mi < 4; ++mi)
#pragma unroll
                for (int ni = 0; ni < 4; ++ni)
                    mma16816(acc[mi][ni], afr[mi], bfr[ni]);
        }

        if (++slot >= STAGES) slot = 0;
    }

    // epilogue
    const int gro = lane >> 2, t4 = lane & 3;
    const int colb = n0 + wn * 32 + t4 * 2;
#pragma unroll
    for (int mi = 0; mi < 4; ++mi) {
#pragma unroll
        for (int half = 0; half < 2; ++half) {
            int r = m0 + wm * 64 + mi * 16 + gro + half * 8;
            float* crow = C + (size_t)r * N;
#pragma unroll
            for (int ni = 0; ni < 4; ++ni) {
                int col = colb + ni * 8;
                float x = acc[mi][ni][half * 2 + 0] + bias[col];
                float y = acc[mi][ni][half * 2 + 1] + bias[col + 1];
                if (RELU) { x = fmaxf(x, 0.f); y = fmaxf(y, 0.f); }
                *(float2*)(crow + col) = make_float2(x, y);
            }
        }
    }
}

// ---------------- BN stats (deterministic split-K) ----------------
__global__ __launch_bounds__(256) void colstats_partial(
    const float* __restrict__ X, int N, int rowsPerBlk)
{
    const int c = blockIdx.x * blockDim.x + threadIdx.x;
    const int r0 = blockIdx.y * rowsPerBlk;
    float s = 0.f, q = 0.f;
    for (int r = r0; r < r0 + rowsPerBlk; ++r) {
        float v = X[(size_t)r * N + c];
        s += v; q = fmaf(v, v, q);
    }
    g_psum[blockIdx.y * N + c] = s;
    g_psq [blockIdx.y * N + c] = q;
}
__global__ __launch_bounds__(256) void colstats_final(
    const float* __restrict__ g, const float* __restrict__ beta, int N, float invM)
{
    const int c = blockIdx.x * blockDim.x + threadIdx.x;
    float s = 0.f, q = 0.f;
#pragma unroll 4
    for (int i = 0; i < SPLITS; ++i) { s += g_psum[i * N + c]; q += g_psq[i * N + c]; }
    float m = s * invM;
    float v = q * invM - m * m;
    float sc = g[c] * rsqrtf(v + EPSBN);
    g_scale[c] = sc;
    g_shift[c] = beta[c] - m * sc;
}

// ---------------- launch ----------------
extern "C" void kernel_launch(void* const* d_in, const int* in_sizes, int n_in,
                              void* d_out, int out_size)
{
    const float* ft0   = (const float*)d_in[1];
    const float* ft1   = (const float*)d_in[2];
    const float* ft2   = (const float*)d_in[3];
    const float* key   = (const float*)d_in[4];
    const float* W1    = (const float*)d_in[5];
    const float* b1    = (const float*)d_in[6];
    const float* g1    = (const float*)d_in[7];
    const float* beta1 = (const float*)d_in[8];
    const float* W2    = (const float*)d_in[9];
    const float* b2    = (const float*)d_in[10];
    const float* g2    = (const float*)d_in[11];
    const float* beta2 = (const float*)d_in[12];
    const float* W3    = (const float*)d_in[13];
    const float* b3    = (const float*)d_in[14];
    const float* We    = (const float*)d_in[15];
    const float* bE    = (const float*)d_in[16];

    float* out     = (float*)d_out;
    float* aligned = out;
    float* extend  = aligned + (size_t)BATCH * CH_H;
    float* ftall   = extend  + (size_t)BATCH * DIM;

    float* buf0;
    __half *Ah, *Bh;
    cudaGetSymbolAddress((void**)&buf0, g_buf0);
    cudaGetSymbolAddress((void**)&Ah, g_Ah);
    cudaGetSymbolAddress((void**)&Bh, g_Bh);

    cudaFuncSetAttribute(gemm_mma<0>, cudaFuncAttributeMaxDynamicSharedMemorySize, SMEM_GEMM);
    cudaFuncSetAttribute(gemm_mma<1>, cudaFuncAttributeMaxDynamicSharedMemorySize, SMEM_GEMM);

    const int MT = BATCH / BM;  // 64

    // 1) score + reweight + pack A1
    score_pack<<<BATCH, 512>>>(ft0, ft1, ft2, key, ftall, Ah);

    // 2) layer 1: y1 = ftall @ W1 + b1  (K = 6144)
    pack_W_t<<<dim3(DIM / 32, CH_H / 32), 256>>>(W1, Bh, DIM, CH_H);
    gemm_mma<0><<<dim3(CH_H / BN, MT), 256, SMEM_GEMM>>>(Ah, Bh, b1, buf0, CH_H, DIM);
    colstats_partial<<<dim3(CH_H / 256, SPLITS), 256>>>(buf0, CH_H, BATCH / SPLITS);
    colstats_final<<<CH_H / 256, 256>>>(g1, beta1, CH_H, 1.0f / BATCH);
    bn_pack<<<BATCH * CH_H / 8 / 256, 256>>>(buf0, Ah, CH_H);

    // 3) layer 2 (K = 2048)
    pack_W_t<<<dim3(CH_H / 32, CH_H / 32), 256>>>(W2, Bh, CH_H, CH_H);
    gemm_mma<0><<<dim3(CH_H / BN, MT), 256, SMEM_GEMM>>>(Ah, Bh, b2, buf0, CH_H, CH_H);
    colstats_partial<<<dim3(CH_H / 256, SPLITS), 256>>>(buf0, CH_H, BATCH / SPLITS);
    colstats_final<<<CH_H / 256, 256>>>(g2, beta2, CH_H, 1.0f / BATCH);
    bn_pack<<<BATCH * CH_H / 8 / 256, 256>>>(buf0, Ah, CH_H);

    // 4) layer 3: aligned = relu(h2 @ W3 + b3)
    pack_W_t<<<dim3(CH_H / 32, CH_H / 32), 256>>>(W3, Bh, CH_H, CH_H);
    gemm_mma<1><<<dim3(CH_H / BN, MT), 256, SMEM_GEMM>>>(Ah, Bh, b3, aligned, CH_H, CH_H);

    // 5) extend = relu(aligned @ We + bE)
    pack_A_rm<<<BATCH * CH_H / 8 / 256, 256>>>(aligned, Ah);
    pack_W_t<<<dim3(CH_H / 32, DIM / 32), 256>>>(We, Bh, CH_H, DIM);
    gemm_mma<1><<<dim3(DIM / BN, MT), 256, SMEM_GEMM>>>(Ah, Bh, bE, extend, DIM, CH_H);
}